// round 11
// baseline (speedup 1.0000x reference)
#include <cuda_runtime.h>
#include <cuda_fp16.h>
#include <cstdint>
#include <math.h>

// Problem constants
#define NE    1024
#define NH    16
#define HS    64
#define TT    2048
#define BB    2
#define BT    (BB*TT)   // 4096
#define FF    4096
#define LN_EPS 1e-5f
#define SQ3   (3*NE)    // fused qkv row stride

// ---------------- scratch (device globals) ----------------
__device__ __half g_h[(size_t)BT*NE];
__device__ __half g_qkv[(size_t)BT*SQ3];
__device__ __half g_at[(size_t)BT*NE];
__device__ __half g_ff[(size_t)BT*FF];
// fp16 weights, SAME [K,N] layout as source (no transpose)
__device__ __half g_wqkv[(size_t)NE*SQ3];   // [1024][3072] = Wq|Wk|Wv
__device__ __half g_wo[(size_t)NE*NE];
__device__ __half g_w1[(size_t)NE*FF];
__device__ __half g_w2[(size_t)FF*NE];

// ---------------- PTX helpers ----------------
__device__ __forceinline__ uint32_t smem_u32(const void* p) {
    uint32_t a;
    asm("{ .reg .u64 t; cvta.to.shared.u64 t, %1; cvt.u32.u64 %0, t; }" : "=r"(a) : "l"(p));
    return a;
}

__device__ __forceinline__ void ldsm4(uint32_t* r, uint32_t addr) {
    asm volatile("ldmatrix.sync.aligned.m8n8.x4.shared.b16 {%0,%1,%2,%3}, [%4];"
        : "=r"(r[0]), "=r"(r[1]), "=r"(r[2]), "=r"(r[3]) : "r"(addr));
}

__device__ __forceinline__ void ldsm4t(uint32_t* r, uint32_t addr) {
    asm volatile("ldmatrix.sync.aligned.m8n8.x4.trans.shared.b16 {%0,%1,%2,%3}, [%4];"
        : "=r"(r[0]), "=r"(r[1]), "=r"(r[2]), "=r"(r[3]) : "r"(addr));
}

// fp32-accumulate mma (kept for attention)
__device__ __forceinline__ void mma16816(float* c, const uint32_t* a, const uint32_t* b) {
    asm volatile("mma.sync.aligned.m16n8k16.row.col.f32.f16.f16.f32 "
        "{%0,%1,%2,%3}, {%4,%5,%6,%7}, {%8,%9}, {%0,%1,%2,%3};"
        : "+f"(c[0]), "+f"(c[1]), "+f"(c[2]), "+f"(c[3])
        : "r"(a[0]), "r"(a[1]), "r"(a[2]), "r"(a[3]), "r"(b[0]), "r"(b[1]));
}

// fp16-accumulate mma (GEMM mainloop experiment; same (row,col) frag map, 2 regs)
__device__ __forceinline__ void mma16816h(uint32_t* c, const uint32_t* a, const uint32_t* b) {
    asm volatile("mma.sync.aligned.m16n8k16.row.col.f16.f16.f16.f16 "
        "{%0,%1}, {%2,%3,%4,%5}, {%6,%7}, {%0,%1};"
        : "+r"(c[0]), "+r"(c[1])
        : "r"(a[0]), "r"(a[1]), "r"(a[2]), "r"(a[3]), "r"(b[0]), "r"(b[1]));
}

__device__ __forceinline__ uint32_t packh(float a, float b) {
    __half2 t = __floats2half2_rn(a, b);
    return *(uint32_t*)&t;
}

// ---------------- weight fp32 -> fp16 streaming cast (layout-preserving) ----------------
__global__ __launch_bounds__(256) void wconv_kernel(
    const float* __restrict__ W, __half* __restrict__ T,
    int N, int outN, int colOff, int total4)
{
    const int idx = blockIdx.x * 256 + threadIdx.x;
    if (idx >= total4) return;
    const int e = idx * 4;
    const int k = e / N, n = e - k * N;
    const float4 v = *(const float4*)(W + (size_t)k * N + n);
    __half* o = T + (size_t)k * outN + colOff + n;
    *(__half2*)o       = __floats2half2_rn(v.x, v.y);
    *(__half2*)(o + 2) = __floats2half2_rn(v.z, v.w);
}

// ---------------- LayerNorm -> fp16, warp-per-row (no barriers) ----------------
__global__ __launch_bounds__(256) void ln_kernel(
    const float* __restrict__ X, const float* __restrict__ G,
    const float* __restrict__ Be, __half* __restrict__ Y)
{
    const int warp = threadIdx.x >> 5, lane = threadIdx.x & 31;
    const int row = blockIdx.x * 8 + warp;
    const float4* xr = (const float4*)(X + (size_t)row * NE);

    float4 xv[8];
    float s = 0.f, ss = 0.f;
    #pragma unroll
    for (int i = 0; i < 8; i++) {
        xv[i] = xr[i * 32 + lane];
        s  += xv[i].x + xv[i].y + xv[i].z + xv[i].w;
        ss += xv[i].x*xv[i].x + xv[i].y*xv[i].y + xv[i].z*xv[i].z + xv[i].w*xv[i].w;
    }
    #pragma unroll
    for (int o = 16; o > 0; o >>= 1) {
        s  += __shfl_xor_sync(0xffffffffu, s, o);
        ss += __shfl_xor_sync(0xffffffffu, ss, o);
    }
    const float mu   = s * (1.0f / NE);
    const float var  = ss * (1.0f / NE) - mu * mu;
    const float rstd = rsqrtf(var + LN_EPS);

    __half2* yp = (__half2*)(Y + (size_t)row * NE);
    #pragma unroll
    for (int i = 0; i < 8; i++) {
        const float4 gv = ((const float4*)G)[i * 32 + lane];
        const float4 bv = ((const float4*)Be)[i * 32 + lane];
        const int e2 = (i * 32 + lane) * 2;
        yp[e2]     = __floats2half2_rn((xv[i].x - mu) * rstd * gv.x + bv.x,
                                       (xv[i].y - mu) * rstd * gv.y + bv.y);
        yp[e2 + 1] = __floats2half2_rn((xv[i].z - mu) * rstd * gv.z + bv.z,
                                       (xv[i].w - mu) * rstd * gv.w + bv.w);
    }
}

// ---------------- mma.sync fp16 GEMM, B in natural [K,N] layout ----------------
// C[M,N] = A[M,K] @ W[K,N]. fp16 accumulate within each K=32 chunk (2 MMAs),
// drained to fp32 every chunk (bounds fp16 accumulation chains).
#define BK 32
#define STAGES 3
#define AROWBG 80
#define AMATBG (128*AROWBG)          // 10240
#define BROWBG 272                   // 128 fp16 = 256B data + 16B pad
#define BMATBG (32*BROWBG)           // 8704
#define STAGEB (AMATBG + BMATBG)     // 18944
#define SMEMB (STAGES*STAGEB)        // 56832

template<bool BIAS, bool RELU, bool RES, bool OUTF32, bool OUTH>
__global__ __launch_bounds__(256) void mma_gemm(
    const __half* __restrict__ A, const __half* __restrict__ B,
    const float* __restrict__ bias, const float* __restrict__ res,
    float* __restrict__ Cf, __half* __restrict__ Ch, int M, int N, int K)
{
    extern __shared__ char smem[];
    const uint32_t sb = smem_u32(smem);
    const int tid = threadIdx.x;
    const int warp = tid >> 5, lane = tid & 31;
    const int n0 = blockIdx.x * 128, m0 = blockIdx.y * 128;
    const int Ku4 = K >> 3, Nu4 = N >> 3;
    const int nch = K / BK;

    auto issue = [&](int kc, int s) {
        if (kc < nch) {
            const uint32_t stage = sb + (uint32_t)s * STAGEB;
            #pragma unroll
            for (int q = 0; q < 4; q++) {
                const int idx = q * 256 + tid;
                if (idx < 512) {            // A: 128 rows x 4 chunks
                    const int row = idx >> 2, u = idx & 3;
                    const uint4* g = (const uint4*)A + (size_t)(m0 + row) * Ku4 + kc * 4 + u;
                    const uint32_t sa = stage + row * AROWBG + u * 16;
                    asm volatile("cp.async.cg.shared.global [%0], [%1], 16;"
                                 :: "r"(sa), "l"(g));
                } else {                    // B: 32 k-rows x 16 chunks
                    const int wi = idx - 512;
                    const int row = wi >> 4, u = wi & 15;
                    const uint4* g = (const uint4*)B + (size_t)(kc * 32 + row) * Nu4 + (n0 >> 3) + u;
                    const uint32_t sa = stage + AMATBG + row * BROWBG + u * 16;
                    asm volatile("cp.async.cg.shared.global [%0], [%1], 16;"
                                 :: "r"(sa), "l"(g));
                }
            }
        }
        asm volatile("cp.async.commit_group;" ::: "memory");
    };

    float acc[4][4][4];
    #pragma unroll
    for (int i = 0; i < 4; i++)
        #pragma unroll
        for (int j = 0; j < 4; j++)
            #pragma unroll
            for (int r = 0; r < 4; r++) acc[i][j][r] = 0.f;

    const int wm = (warp >> 2) * 64;
    const int wn = (warp & 3) * 32;

    const int amat = lane >> 3;
    const int arr  = ((amat & 1) << 3) + (lane & 7);
    const int brow  = ((amat & 1) << 3) + (lane & 7);   // trans-unit row (k)
    const int bhsel = lane >> 4;                        // n-halfword select

    issue(0, 0);
    issue(1, 1);

    for (int kc = 0; kc < nch; kc++) {
        const int s = kc % STAGES;
        asm volatile("cp.async.wait_group 1;" ::: "memory");
        __syncthreads();
        issue(kc + 2, (kc + 2) % STAGES);

        const uint32_t stage = sb + (uint32_t)s * STAGEB;
        const uint32_t aBase = stage;
        const uint32_t bBase = stage + AMATBG;

        // fp16 chunk accumulators (zeroed per K=32 chunk)
        uint32_t chk[4][4][2];
        #pragma unroll
        for (int i = 0; i < 4; i++)
            #pragma unroll
            for (int j = 0; j < 4; j++) { chk[i][j][0] = 0u; chk[i][j][1] = 0u; }

        #pragma unroll
        for (int ks = 0; ks < 2; ks++) {
            uint32_t ah[4][4], bh[4][2];
            const int au = ks * 2 + (amat >> 1);
            #pragma unroll
            for (int i = 0; i < 4; i++) {
                const uint32_t off = (uint32_t)((wm + i * 16 + arr) * AROWBG + au * 16);
                ldsm4(ah[i], aBase + off);
            }
            #pragma unroll
            for (int jp = 0; jp < 2; jp++) {
                const uint32_t off = (uint32_t)((ks * 16 + brow) * BROWBG
                                                + (wn + jp * 16) * 2 + bhsel * 16);
                uint32_t t[4];
                ldsm4t(t, bBase + off);
                bh[jp*2][0] = t[0]; bh[jp*2][1] = t[1];
                bh[jp*2+1][0] = t[2]; bh[jp*2+1][1] = t[3];
            }
            #pragma unroll
            for (int i = 0; i < 4; i++)
                #pragma unroll
                for (int j = 0; j < 4; j++) mma16816h(chk[i][j], ah[i], bh[j]);
        }

        // drain fp16 chunk accumulators into fp32
        #pragma unroll
        for (int i = 0; i < 4; i++)
            #pragma unroll
            for (int j = 0; j < 4; j++) {
                const float2 lo = __half22float2(*(__half2*)&chk[i][j][0]);
                const float2 hi = __half22float2(*(__half2*)&chk[i][j][1]);
                acc[i][j][0] += lo.x; acc[i][j][1] += lo.y;
                acc[i][j][2] += hi.x; acc[i][j][3] += hi.y;
            }
        __syncthreads();
    }
    asm volatile("cp.async.wait_group 0;" ::: "memory");

    const int qrow = lane >> 2, qcol = (lane & 3) * 2;
    #pragma unroll
    for (int i = 0; i < 4; i++) {
        #pragma unroll
        for (int j = 0; j < 4; j++) {
            const int col = n0 + wn + j * 8 + qcol;
            float2 bv = make_float2(0.f, 0.f);
            if (BIAS) bv = *(const float2*)(bias + col);
            #pragma unroll
            for (int half_ = 0; half_ < 2; half_++) {
                const int row = m0 + wm + i * 16 + qrow + half_ * 8;
                float v0 = acc[i][j][half_ * 2 + 0];
                float v1 = acc[i][j][half_ * 2 + 1];
                if (BIAS) { v0 += bv.x; v1 += bv.y; }
                if (RELU) { v0 = fmaxf(v0, 0.f); v1 = fmaxf(v1, 0.f); }
                if (RES) {
                    float2 r = *(const float2*)(res + (size_t)row * N + col);
                    v0 += r.x; v1 += r.y;
                }
                if (OUTF32)
                    *(float2*)(Cf + (size_t)row * N + col) = make_float2(v0, v1);
                if (OUTH)
                    *(__half2*)(Ch + (size_t)row * N + col) = __floats2half2_rn(v0, v1);
            }
        }
    }
}

// ---------------- tensor-core causal flash attention (fp16, fused-qkv input) ----------------
#define AROWB 144
#define AQMAT (128*AROWB)               // 18432
#define AKMAT (64*AROWB)                // 9216
#define ASTAGE (2*AKMAT)                // K, V
#define ASMEM (AQMAT + 2*ASTAGE)        // 55296

__global__ __launch_bounds__(256) void attn_mma_kernel(
    const __half* __restrict__ QKV, __half* __restrict__ O)
{
    extern __shared__ char smem[];
    const uint32_t sb = smem_u32(smem);
    const int tid = threadIdx.x, warp = tid >> 5, lane = tid & 31;
    const int bh = blockIdx.y, b = bh >> 4, h = bh & 15;
    const int qt = gridDim.x - 1 - blockIdx.x;     // heavy tiles first
    const int q0 = qt * 128;
    const size_t qbase = (size_t)b * TT * SQ3 + h * HS;
    const size_t obase = (size_t)b * TT * NE + h * HS;

    {
        #pragma unroll
        for (int c = 0; c < 4; c++) {
            const int idx = c * 256 + tid;
            const int row = idx >> 3, u = idx & 7;
            const uint4* g = (const uint4*)(QKV + qbase + (size_t)(q0 + row) * SQ3) + u;
            const uint32_t sa = sb + row * AROWB + u * 16;
            asm volatile("cp.async.cg.shared.global [%0], [%1], 16;" :: "r"(sa), "l"(g));
        }
        asm volatile("cp.async.commit_group;" ::: "memory");
    }

    auto issue_kv = [&](int t, int s) {
        if (t >= 0) {
            const int k0 = t * 64;
            const uint32_t stage = sb + AQMAT + (uint32_t)s * ASTAGE;
            #pragma unroll
            for (int c = 0; c < 4; c++) {
                const int idx = c * 256 + tid;
                const int mat = idx >> 9, wi = idx & 511;
                const int row = wi >> 3, u = wi & 7;
                const uint4* g = (const uint4*)(QKV + qbase + (mat + 1) * NE
                                                + (size_t)(k0 + row) * SQ3) + u;
                const uint32_t sa = stage + mat * AKMAT + row * AROWB + u * 16;
                asm volatile("cp.async.cg.shared.global [%0], [%1], 16;" :: "r"(sa), "l"(g));
            }
        }
        asm volatile("cp.async.commit_group;" ::: "memory");
    };

    const int ntiles = 2 * (qt + 1);
    issue_kv(0, 0);

    float m[2] = { -1e30f, -1e30f }, l[2] = { 0.f, 0.f };
    float o[8][4];
    #pragma unroll
    for (int nt = 0; nt < 8; nt++)
        #pragma unroll
        for (int e = 0; e < 4; e++) o[nt][e] = 0.f;

    const float scale = 0.03125f;   // 1024^-0.5, faithful to source
    const int amat = lane >> 3;
    const int arr  = ((amat & 1) << 3) + (lane & 7);
    const int ahalf = amat >> 1;
    const int brr  = ((amat >> 1) << 3) + (lane & 7);
    const int bhalf = amat & 1;
    const int vrow  = ((amat & 1) << 3) + (lane & 7);
    const int vhalf = lane >> 4;

    for (int t = 0; t < ntiles; t++) {
        issue_kv((t + 1 < ntiles) ? t + 1 : -1, (t + 1) & 1);
        asm volatile("cp.async.wait_group 1;" ::: "memory");
        __syncthreads();

        const int k0 = t * 64;
        const uint32_t stage = sb + AQMAT + (uint32_t)(t & 1) * ASTAGE;
        const uint32_t kB = stage, vB = stage + AKMAT;

        float s[8][4];
        #pragma unroll
        for (int nt = 0; nt < 8; nt++)
            #pragma unroll
            for (int e = 0; e < 4; e++) s[nt][e] = 0.f;

        #pragma unroll
        for (int kc = 0; kc < 4; kc++) {
            uint32_t af[4];
            ldsm4(af, sb + (uint32_t)((warp * 16 + arr) * AROWB + kc * 32 + ahalf * 16));
            #pragma unroll
            for (int jp = 0; jp < 4; jp++) {
                uint32_t tt[4];
                ldsm4(tt, kB + (uint32_t)((jp * 16 + brr) * AROWB + kc * 32 + bhalf * 16));
                uint32_t b0[2] = { tt[0], tt[1] }, b1[2] = { tt[2], tt[3] };
                mma16816(s[jp * 2],     af, b0);
                mma16816(s[jp * 2 + 1], af, b1);
            }
        }

        const bool domask = (k0 + 63 > q0);
        float mnew[2] = { m[0], m[1] };
        #pragma unroll
        for (int nt = 0; nt < 8; nt++)
            #pragma unroll
            for (int e = 0; e < 4; e++) {
                float v = s[nt][e] * scale;
                if (domask) {
                    const int key = k0 + nt * 8 + (lane & 3) * 2 + (e & 1);
                    const int qq  = q0 + warp * 16 + (lane >> 2) + (e >> 1) * 8;
                    if (key > qq) v = -1e30f;
                }
                s[nt][e] = v;
                mnew[e >> 1] = fmaxf(mnew[e >> 1], v);
            }
        #pragma unroll
        for (int r = 0; r < 2; r++) {
            mnew[r] = fmaxf(mnew[r], __shfl_xor_sync(0xffffffffu, mnew[r], 1));
            mnew[r] = fmaxf(mnew[r], __shfl_xor_sync(0xffffffffu, mnew[r], 2));
        }
        float corr[2], psum[2] = { 0.f, 0.f };
        corr[0] = __expf(m[0] - mnew[0]);
        corr[1] = __expf(m[1] - mnew[1]);
        m[0] = mnew[0]; m[1] = mnew[1];
        #pragma unroll
        for (int nt = 0; nt < 8; nt++)
            #pragma unroll
            for (int e = 0; e < 4; e++) {
                const float p_ = __expf(s[nt][e] - mnew[e >> 1]);
                s[nt][e] = p_;
                psum[e >> 1] += p_;
            }
        #pragma unroll
        for (int r = 0; r < 2; r++) {
            psum[r] += __shfl_xor_sync(0xffffffffu, psum[r], 1);
            psum[r] += __shfl_xor_sync(0xffffffffu, psum[r], 2);
            l[r] = l[r] * corr[r] + psum[r];
        }
        #pragma unroll
        for (int nt = 0; nt < 8; nt++)
            #pragma unroll
            for (int e = 0; e < 4; e++) o[nt][e] *= corr[e >> 1];

        #pragma unroll
        for (int kk = 0; kk < 4; kk++) {
            uint32_t ph[4];
            ph[0] = packh(s[2*kk][0],   s[2*kk][1]);
            ph[1] = packh(s[2*kk][2],   s[2*kk][3]);
            ph[2] = packh(s[2*kk+1][0], s[2*kk+1][1]);
            ph[3] = packh(s[2*kk+1][2], s[2*kk+1][3]);
            #pragma unroll
            for (int jp = 0; jp < 4; jp++) {
                const uint32_t va =
                    (uint32_t)((kk * 16 + vrow) * AROWB + jp * 32 + vhalf * 16);
                uint32_t th[4];
                ldsm4t(th, vB + va);
                uint32_t bh0[2] = { th[0], th[1] }, bh1[2] = { th[2], th[3] };
                mma16816(o[jp*2],   ph, bh0);
                mma16816(o[jp*2+1], ph, bh1);
            }
        }
        __syncthreads();
    }

    const float inv0 = 1.0f / l[0], inv1 = 1.0f / l[1];
    const int r0 = q0 + warp * 16 + (lane >> 2);
    const int r1 = r0 + 8;
    #pragma unroll
    for (int nt = 0; nt < 8; nt++) {
        const int col = nt * 8 + (lane & 3) * 2;
        *(__half2*)(O + obase + (size_t)r0 * NE + col) =
            __floats2half2_rn(o[nt][0] * inv0, o[nt][1] * inv0);
        *(__half2*)(O + obase + (size_t)r1 * NE + col) =
            __floats2half2_rn(o[nt][2] * inv1, o[nt][3] * inv1);
    }
}

// ---------------- launch ----------------
extern "C" void kernel_launch(void* const* d_in, const int* in_sizes, int n_in,
                              void* d_out, int out_size)
{
    const float* x  = (const float*)d_in[0];
    const float* Wq = (const float*)d_in[1];
    const float* Wk = (const float*)d_in[2];
    const float* Wv = (const float*)d_in[3];
    const float* Wo = (const float*)d_in[4];
    const float* bo = (const float*)d_in[5];
    const float* W1 = (const float*)d_in[6];
    const float* b1 = (const float*)d_in[7];
    const float* W2 = (const float*)d_in[8];
    const float* b2 = (const float*)d_in[9];
    const float* g1  = (const float*)d_in[10];
    const float* be1 = (const float*)d_in[11];
    const float* g2  = (const float*)d_in[12];
    const float* be2 = (const float*)d_in[13];
    float* out = (float*)d_out;

    __half *h, *qkv, *at, *ff, *wqkv, *wo, *w1, *w2;
    cudaGetSymbolAddress((void**)&h, g_h);
    cudaGetSymbolAddress((void**)&qkv, g_qkv);
    cudaGetSymbolAddress((void**)&at, g_at);
    cudaGetSymbolAddress((void**)&ff, g_ff);
    cudaGetSymbolAddress((void**)&wqkv, g_wqkv);
    cudaGetSymbolAddress((void**)&wo, g_wo);
    cudaGetSymbolAddress((void**)&w1, g_w1);
    cudaGetSymbolAddress((void**)&w2, g_w2);

    cudaFuncSetAttribute(mma_gemm<false,false,false,false,true>,
                         cudaFuncAttributeMaxDynamicSharedMemorySize, SMEMB);
    cudaFuncSetAttribute(mma_gemm<true,false,true,true,false>,
                         cudaFuncAttributeMaxDynamicSharedMemorySize, SMEMB);
    cudaFuncSetAttribute(mma_gemm<true,true,false,false,true>,
                         cudaFuncAttributeMaxDynamicSharedMemorySize, SMEMB);
    cudaFuncSetAttribute(attn_mma_kernel,
                         cudaFuncAttributeMaxDynamicSharedMemorySize, ASMEM);

    const int t4_ne  = NE * NE / 4;     // 262144 -> 1024 blocks
    const int t4_ff  = NE * FF / 4;     // 1048576 -> 4096 blocks

    wconv_kernel<<<t4_ne/256, 256>>>(Wq, wqkv, NE, SQ3, 0,    t4_ne);      // 0
    wconv_kernel<<<t4_ne/256, 256>>>(Wk, wqkv, NE, SQ3, NE,   t4_ne);      // 1
    wconv_kernel<<<t4_ne/256, 256>>>(Wv, wqkv, NE, SQ3, 2*NE, t4_ne);      // 2
    ln_kernel<<<BT/8, 256>>>(x, g1, be1, h);                               // 3
    wconv_kernel<<<t4_ne/256, 256>>>(Wo, wo, NE, NE, 0, t4_ne);            // 4
    dim3 gQKV(SQ3/128, BT/128);
    mma_gemm<false,false,false,false,true><<<gQKV, 256, SMEMB>>>(
        h, wqkv, nullptr, nullptr, nullptr, qkv, BT, SQ3, NE);             // 5
    dim3 gAtt(TT/128, BB*NH);
    attn_mma_kernel<<<gAtt, 256, ASMEM>>>(qkv, at);                        // 6
    dim3 gO(NE/128, BT/128);
    mma_gemm<true,false,true,true,false><<<gO, 256, SMEMB>>>(
        at, wo, bo, x, out, nullptr, BT, NE, NE);                          // 7
    ln_kernel<<<BT/8, 256>>>(out, g2, be2, h);                             // 8
    wconv_kernel<<<t4_ff/256, 256>>>(W1, w1, FF, FF, 0, t4_ff);            // 9
    dim3 gF1(FF/128, BT/128);
    mma_gemm<true,true,false,false,true><<<gF1, 256, SMEMB>>>(
        h, w1, b1, nullptr, nullptr, ff, BT, FF, NE);                      // 10
    wconv_kernel<<<t4_ff/256, 256>>>(W2, w2, NE, NE, 0, t4_ff);            // 11
    dim3 gF2(NE/128, BT/128);
    mma_gemm<true,false,true,true,false><<<gF2, 256, SMEMB>>>(
        ff, w2, b2, out, out, nullptr, BT, NE, FF);                        // 12
}

// round 12
// speedup vs baseline: 1.1552x; 1.1552x over previous
#include <cuda_runtime.h>
#include <cuda_fp16.h>
#include <cstdint>
#include <math.h>

// Problem constants
#define NE    1024
#define NH    16
#define HS    64
#define TT    2048
#define BB    2
#define BT    (BB*TT)   // 4096
#define FF    4096
#define LN_EPS 1e-5f
#define SQ3   (3*NE)    // fused qkv row stride

// ---------------- scratch (device globals) ----------------
__device__ __half g_h[(size_t)BT*NE];
__device__ __half g_qkv[(size_t)BT*SQ3];
__device__ __half g_at[(size_t)BT*NE];
__device__ __half g_ff[(size_t)BT*FF];
// fp16 weights, SAME [K,N] layout as source (no transpose)
__device__ __half g_wqkv[(size_t)NE*SQ3];   // [1024][3072] = Wq|Wk|Wv
__device__ __half g_wo[(size_t)NE*NE];
__device__ __half g_w1[(size_t)NE*FF];
__device__ __half g_w2[(size_t)FF*NE];

// ---------------- PTX helpers ----------------
__device__ __forceinline__ uint32_t smem_u32(const void* p) {
    uint32_t a;
    asm("{ .reg .u64 t; cvta.to.shared.u64 t, %1; cvt.u32.u64 %0, t; }" : "=r"(a) : "l"(p));
    return a;
}

__device__ __forceinline__ void ldsm4(uint32_t* r, uint32_t addr) {
    asm volatile("ldmatrix.sync.aligned.m8n8.x4.shared.b16 {%0,%1,%2,%3}, [%4];"
        : "=r"(r[0]), "=r"(r[1]), "=r"(r[2]), "=r"(r[3]) : "r"(addr));
}

__device__ __forceinline__ void ldsm4t(uint32_t* r, uint32_t addr) {
    asm volatile("ldmatrix.sync.aligned.m8n8.x4.trans.shared.b16 {%0,%1,%2,%3}, [%4];"
        : "=r"(r[0]), "=r"(r[1]), "=r"(r[2]), "=r"(r[3]) : "r"(addr));
}

__device__ __forceinline__ void mma16816(float* c, const uint32_t* a, const uint32_t* b) {
    asm volatile("mma.sync.aligned.m16n8k16.row.col.f32.f16.f16.f32 "
        "{%0,%1,%2,%3}, {%4,%5,%6,%7}, {%8,%9}, {%0,%1,%2,%3};"
        : "+f"(c[0]), "+f"(c[1]), "+f"(c[2]), "+f"(c[3])
        : "r"(a[0]), "r"(a[1]), "r"(a[2]), "r"(a[3]), "r"(b[0]), "r"(b[1]));
}

__device__ __forceinline__ uint32_t packh(float a, float b) {
    __half2 t = __floats2half2_rn(a, b);
    return *(uint32_t*)&t;
}

// ---------------- weight fp32 -> fp16 streaming casts ----------------
// Fused QKV cast: grid.y in {0,1,2} selects Wq/Wk/Wv; dst col offset = y*NE.
__global__ __launch_bounds__(256) void wconv_qkv_kernel(
    const float* __restrict__ Wq, const float* __restrict__ Wk,
    const float* __restrict__ Wv, __half* __restrict__ T)
{
    const float* W = (blockIdx.y == 0) ? Wq : (blockIdx.y == 1) ? Wk : Wv;
    const int colOff = blockIdx.y * NE;
    const int idx = blockIdx.x * 256 + threadIdx.x;     // NE*NE/4 chunks
    const int e = idx * 4;
    const int k = e >> 10, n = e & 1023;
    const float4 v = *(const float4*)(W + (size_t)k * NE + n);
    __half* o = T + (size_t)k * SQ3 + colOff + n;
    *(__half2*)o       = __floats2half2_rn(v.x, v.y);
    *(__half2*)(o + 2) = __floats2half2_rn(v.z, v.w);
}

__global__ __launch_bounds__(256) void wconv_kernel(
    const float* __restrict__ W, __half* __restrict__ T,
    int N, int total4)
{
    const int idx = blockIdx.x * 256 + threadIdx.x;
    if (idx >= total4) return;
    const int e = idx * 4;
    const int k = e / N, n = e - k * N;
    const float4 v = *(const float4*)(W + (size_t)k * N + n);
    __half* o = T + (size_t)k * N + n;
    *(__half2*)o       = __floats2half2_rn(v.x, v.y);
    *(__half2*)(o + 2) = __floats2half2_rn(v.z, v.w);
}

// ---------------- LayerNorm -> fp16, warp-per-row (no barriers) ----------------
__global__ __launch_bounds__(256) void ln_kernel(
    const float* __restrict__ X, const float* __restrict__ G,
    const float* __restrict__ Be, __half* __restrict__ Y)
{
    const int warp = threadIdx.x >> 5, lane = threadIdx.x & 31;
    const int row = blockIdx.x * 8 + warp;
    const float4* xr = (const float4*)(X + (size_t)row * NE);

    float4 xv[8];
    float s = 0.f, ss = 0.f;
    #pragma unroll
    for (int i = 0; i < 8; i++) {
        xv[i] = xr[i * 32 + lane];
        s  += xv[i].x + xv[i].y + xv[i].z + xv[i].w;
        ss += xv[i].x*xv[i].x + xv[i].y*xv[i].y + xv[i].z*xv[i].z + xv[i].w*xv[i].w;
    }
    #pragma unroll
    for (int o = 16; o > 0; o >>= 1) {
        s  += __shfl_xor_sync(0xffffffffu, s, o);
        ss += __shfl_xor_sync(0xffffffffu, ss, o);
    }
    const float mu   = s * (1.0f / NE);
    const float var  = ss * (1.0f / NE) - mu * mu;
    const float rstd = rsqrtf(var + LN_EPS);

    __half2* yp = (__half2*)(Y + (size_t)row * NE);
    #pragma unroll
    for (int i = 0; i < 8; i++) {
        const float4 gv = ((const float4*)G)[i * 32 + lane];
        const float4 bv = ((const float4*)Be)[i * 32 + lane];
        const int e2 = (i * 32 + lane) * 2;
        yp[e2]     = __floats2half2_rn((xv[i].x - mu) * rstd * gv.x + bv.x,
                                       (xv[i].y - mu) * rstd * gv.y + bv.y);
        yp[e2 + 1] = __floats2half2_rn((xv[i].z - mu) * rstd * gv.z + bv.z,
                                       (xv[i].w - mu) * rstd * gv.w + bv.w);
    }
}

// ---------------- persistent mma.sync fp16 GEMM (fp32 accum), B natural [K,N] ----------------
#define BK 32
#define STAGES 3
#define AROWBG 80
#define AMATBG (128*AROWBG)          // 10240
#define BROWBG 272                   // 128 fp16 = 256B data + 16B pad
#define BMATBG (32*BROWBG)           // 8704
#define STAGEB (AMATBG + BMATBG)     // 18944
#define SMEMB (STAGES*STAGEB)        // 56832

template<bool BIAS, bool RELU, bool RES, bool OUTF32, bool OUTH>
__global__ __launch_bounds__(256) void mma_gemm(
    const __half* __restrict__ A, const __half* __restrict__ B,
    const float* __restrict__ bias, const float* __restrict__ res,
    float* __restrict__ Cf, __half* __restrict__ Ch,
    int M, int N, int K, int ntn)
{
    extern __shared__ char smem[];
    const uint32_t sb = smem_u32(smem);
    const int tid = threadIdx.x;
    const int warp = tid >> 5, lane = tid & 31;
    const int Ku4 = K >> 3, Nu4 = N >> 3;
    const int nch = K / BK;
    const int ntiles = (M >> 7) * ntn;

    const int wm = (warp >> 2) * 64;
    const int wn = (warp & 3) * 32;
    const int amat = lane >> 3;
    const int arr  = ((amat & 1) << 3) + (lane & 7);
    const int brow  = ((amat & 1) << 3) + (lane & 7);
    const int bhsel = lane >> 4;
    const int qrow = lane >> 2, qcol = (lane & 3) * 2;

    for (int tile = blockIdx.x; tile < ntiles; tile += gridDim.x) {
        const int m0 = (tile / ntn) << 7;
        const int n0 = (tile - (tile / ntn) * ntn) << 7;

        auto issue = [&](int kc, int s) {
            if (kc < nch) {
                const uint32_t stage = sb + (uint32_t)s * STAGEB;
                #pragma unroll
                for (int q = 0; q < 4; q++) {
                    const int idx = q * 256 + tid;
                    if (idx < 512) {            // A: 128 rows x 4 chunks
                        const int row = idx >> 2, u = idx & 3;
                        const uint4* g = (const uint4*)A + (size_t)(m0 + row) * Ku4 + kc * 4 + u;
                        const uint32_t sa = stage + row * AROWBG + u * 16;
                        asm volatile("cp.async.cg.shared.global [%0], [%1], 16;"
                                     :: "r"(sa), "l"(g));
                    } else {                    // B: 32 k-rows x 16 chunks
                        const int wi = idx - 512;
                        const int row = wi >> 4, u = wi & 15;
                        const uint4* g = (const uint4*)B + (size_t)(kc * 32 + row) * Nu4 + (n0 >> 3) + u;
                        const uint32_t sa = stage + AMATBG + row * BROWBG + u * 16;
                        asm volatile("cp.async.cg.shared.global [%0], [%1], 16;"
                                     :: "r"(sa), "l"(g));
                    }
                }
            }
            asm volatile("cp.async.commit_group;" ::: "memory");
        };

        float acc[4][4][4];
        #pragma unroll
        for (int i = 0; i < 4; i++)
            #pragma unroll
            for (int j = 0; j < 4; j++)
                #pragma unroll
                for (int r = 0; r < 4; r++) acc[i][j][r] = 0.f;

        issue(0, 0);
        issue(1, 1);

        for (int kc = 0; kc < nch; kc++) {
            const int s = kc % STAGES;
            asm volatile("cp.async.wait_group 1;" ::: "memory");
            __syncthreads();
            issue(kc + 2, (kc + 2) % STAGES);

            const uint32_t stage = sb + (uint32_t)s * STAGEB;
            const uint32_t aBase = stage;
            const uint32_t bBase = stage + AMATBG;

            #pragma unroll
            for (int ks = 0; ks < 2; ks++) {
                uint32_t ah[4][4], bh[4][2];
                const int au = ks * 2 + (amat >> 1);
                #pragma unroll
                for (int i = 0; i < 4; i++) {
                    const uint32_t off = (uint32_t)((wm + i * 16 + arr) * AROWBG + au * 16);
                    ldsm4(ah[i], aBase + off);
                }
                #pragma unroll
                for (int jp = 0; jp < 2; jp++) {
                    const uint32_t off = (uint32_t)((ks * 16 + brow) * BROWBG
                                                    + (wn + jp * 16) * 2 + bhsel * 16);
                    uint32_t t[4];
                    ldsm4t(t, bBase + off);
                    bh[jp*2][0] = t[0]; bh[jp*2][1] = t[1];
                    bh[jp*2+1][0] = t[2]; bh[jp*2+1][1] = t[3];
                }
                #pragma unroll
                for (int i = 0; i < 4; i++)
                    #pragma unroll
                    for (int j = 0; j < 4; j++) mma16816(acc[i][j], ah[i], bh[j]);
            }
            __syncthreads();
        }
        asm volatile("cp.async.wait_group 0;" ::: "memory");

        #pragma unroll
        for (int i = 0; i < 4; i++) {
            #pragma unroll
            for (int j = 0; j < 4; j++) {
                const int col = n0 + wn + j * 8 + qcol;
                float2 bv = make_float2(0.f, 0.f);
                if (BIAS) bv = *(const float2*)(bias + col);
                #pragma unroll
                for (int half_ = 0; half_ < 2; half_++) {
                    const int row = m0 + wm + i * 16 + qrow + half_ * 8;
                    float v0 = acc[i][j][half_ * 2 + 0];
                    float v1 = acc[i][j][half_ * 2 + 1];
                    if (BIAS) { v0 += bv.x; v1 += bv.y; }
                    if (RELU) { v0 = fmaxf(v0, 0.f); v1 = fmaxf(v1, 0.f); }
                    if (RES) {
                        float2 r = *(const float2*)(res + (size_t)row * N + col);
                        v0 += r.x; v1 += r.y;
                    }
                    if (OUTF32)
                        *(float2*)(Cf + (size_t)row * N + col) = make_float2(v0, v1);
                    if (OUTH)
                        *(__half2*)(Ch + (size_t)row * N + col) = __floats2half2_rn(v0, v1);
                }
            }
        }
        __syncthreads();   // guard smem reuse across tiles
    }
}

// ---------------- tensor-core causal flash attention (fp16, fused-qkv input) ----------------
#define AROWB 144
#define AQMAT (128*AROWB)               // 18432
#define AKMAT (64*AROWB)                // 9216
#define ASTAGE (2*AKMAT)                // K, V
#define ASMEM (AQMAT + 2*ASTAGE)        // 55296

__global__ __launch_bounds__(256) void attn_mma_kernel(
    const __half* __restrict__ QKV, __half* __restrict__ O)
{
    extern __shared__ char smem[];
    const uint32_t sb = smem_u32(smem);
    const int tid = threadIdx.x, warp = tid >> 5, lane = tid & 31;
    const int bh = blockIdx.y, b = bh >> 4, h = bh & 15;
    const int qt = gridDim.x - 1 - blockIdx.x;     // heavy tiles first
    const int q0 = qt * 128;
    const size_t qbase = (size_t)b * TT * SQ3 + h * HS;
    const size_t obase = (size_t)b * TT * NE + h * HS;

    {
        #pragma unroll
        for (int c = 0; c < 4; c++) {
            const int idx = c * 256 + tid;
            const int row = idx >> 3, u = idx & 7;
            const uint4* g = (const uint4*)(QKV + qbase + (size_t)(q0 + row) * SQ3) + u;
            const uint32_t sa = sb + row * AROWB + u * 16;
            asm volatile("cp.async.cg.shared.global [%0], [%1], 16;" :: "r"(sa), "l"(g));
        }
        asm volatile("cp.async.commit_group;" ::: "memory");
    }

    auto issue_kv = [&](int t, int s) {
        if (t >= 0) {
            const int k0 = t * 64;
            const uint32_t stage = sb + AQMAT + (uint32_t)s * ASTAGE;
            #pragma unroll
            for (int c = 0; c < 4; c++) {
                const int idx = c * 256 + tid;
                const int mat = idx >> 9, wi = idx & 511;
                const int row = wi >> 3, u = wi & 7;
                const uint4* g = (const uint4*)(QKV + qbase + (mat + 1) * NE
                                                + (size_t)(k0 + row) * SQ3) + u;
                const uint32_t sa = stage + mat * AKMAT + row * AROWB + u * 16;
                asm volatile("cp.async.cg.shared.global [%0], [%1], 16;" :: "r"(sa), "l"(g));
            }
        }
        asm volatile("cp.async.commit_group;" ::: "memory");
    };

    const int ntiles = 2 * (qt + 1);
    issue_kv(0, 0);

    float m[2] = { -1e30f, -1e30f }, l[2] = { 0.f, 0.f };
    float o[8][4];
    #pragma unroll
    for (int nt = 0; nt < 8; nt++)
        #pragma unroll
        for (int e = 0; e < 4; e++) o[nt][e] = 0.f;

    const float scale = 0.03125f;   // 1024^-0.5, faithful to source
    const int amat = lane >> 3;
    const int arr  = ((amat & 1) << 3) + (lane & 7);
    const int ahalf = amat >> 1;
    const int brr  = ((amat >> 1) << 3) + (lane & 7);
    const int bhalf = amat & 1;
    const int vrow  = ((amat & 1) << 3) + (lane & 7);
    const int vhalf = lane >> 4;

    for (int t = 0; t < ntiles; t++) {
        issue_kv((t + 1 < ntiles) ? t + 1 : -1, (t + 1) & 1);
        asm volatile("cp.async.wait_group 1;" ::: "memory");
        __syncthreads();

        const int k0 = t * 64;
        const uint32_t stage = sb + AQMAT + (uint32_t)(t & 1) * ASTAGE;
        const uint32_t kB = stage, vB = stage + AKMAT;

        float s[8][4];
        #pragma unroll
        for (int nt = 0; nt < 8; nt++)
            #pragma unroll
            for (int e = 0; e < 4; e++) s[nt][e] = 0.f;

        #pragma unroll
        for (int kc = 0; kc < 4; kc++) {
            uint32_t af[4];
            ldsm4(af, sb + (uint32_t)((warp * 16 + arr) * AROWB + kc * 32 + ahalf * 16));
            #pragma unroll
            for (int jp = 0; jp < 4; jp++) {
                uint32_t tt[4];
                ldsm4(tt, kB + (uint32_t)((jp * 16 + brr) * AROWB + kc * 32 + bhalf * 16));
                uint32_t b0[2] = { tt[0], tt[1] }, b1[2] = { tt[2], tt[3] };
                mma16816(s[jp * 2],     af, b0);
                mma16816(s[jp * 2 + 1], af, b1);
            }
        }

        const bool domask = (k0 + 63 > q0);
        float mnew[2] = { m[0], m[1] };
        #pragma unroll
        for (int nt = 0; nt < 8; nt++)
            #pragma unroll
            for (int e = 0; e < 4; e++) {
                float v = s[nt][e] * scale;
                if (domask) {
                    const int key = k0 + nt * 8 + (lane & 3) * 2 + (e & 1);
                    const int qq  = q0 + warp * 16 + (lane >> 2) + (e >> 1) * 8;
                    if (key > qq) v = -1e30f;
                }
                s[nt][e] = v;
                mnew[e >> 1] = fmaxf(mnew[e >> 1], v);
            }
        #pragma unroll
        for (int r = 0; r < 2; r++) {
            mnew[r] = fmaxf(mnew[r], __shfl_xor_sync(0xffffffffu, mnew[r], 1));
            mnew[r] = fmaxf(mnew[r], __shfl_xor_sync(0xffffffffu, mnew[r], 2));
        }
        float corr[2], psum[2] = { 0.f, 0.f };
        corr[0] = __expf(m[0] - mnew[0]);
        corr[1] = __expf(m[1] - mnew[1]);
        m[0] = mnew[0]; m[1] = mnew[1];
        #pragma unroll
        for (int nt = 0; nt < 8; nt++)
            #pragma unroll
            for (int e = 0; e < 4; e++) {
                const float p_ = __expf(s[nt][e] - mnew[e >> 1]);
                s[nt][e] = p_;
                psum[e >> 1] += p_;
            }
        #pragma unroll
        for (int r = 0; r < 2; r++) {
            psum[r] += __shfl_xor_sync(0xffffffffu, psum[r], 1);
            psum[r] += __shfl_xor_sync(0xffffffffu, psum[r], 2);
            l[r] = l[r] * corr[r] + psum[r];
        }
        #pragma unroll
        for (int nt = 0; nt < 8; nt++)
            #pragma unroll
            for (int e = 0; e < 4; e++) o[nt][e] *= corr[e >> 1];

        #pragma unroll
        for (int kk = 0; kk < 4; kk++) {
            uint32_t ph[4];
            ph[0] = packh(s[2*kk][0],   s[2*kk][1]);
            ph[1] = packh(s[2*kk][2],   s[2*kk][3]);
            ph[2] = packh(s[2*kk+1][0], s[2*kk+1][1]);
            ph[3] = packh(s[2*kk+1][2], s[2*kk+1][3]);
            #pragma unroll
            for (int jp = 0; jp < 4; jp++) {
                const uint32_t va =
                    (uint32_t)((kk * 16 + vrow) * AROWB + jp * 32 + vhalf * 16);
                uint32_t th[4];
                ldsm4t(th, vB + va);
                uint32_t bh0[2] = { th[0], th[1] }, bh1[2] = { th[2], th[3] };
                mma16816(o[jp*2],   ph, bh0);
                mma16816(o[jp*2+1], ph, bh1);
            }
        }
        __syncthreads();
    }

    const float inv0 = 1.0f / l[0], inv1 = 1.0f / l[1];
    const int r0 = q0 + warp * 16 + (lane >> 2);
    const int r1 = r0 + 8;
    #pragma unroll
    for (int nt = 0; nt < 8; nt++) {
        const int col = nt * 8 + (lane & 3) * 2;
        *(__half2*)(O + obase + (size_t)r0 * NE + col) =
            __floats2half2_rn(o[nt][0] * inv0, o[nt][1] * inv0);
        *(__half2*)(O + obase + (size_t)r1 * NE + col) =
            __floats2half2_rn(o[nt][2] * inv1, o[nt][3] * inv1);
    }
}

// ---------------- launch ----------------
extern "C" void kernel_launch(void* const* d_in, const int* in_sizes, int n_in,
                              void* d_out, int out_size)
{
    const float* x  = (const float*)d_in[0];
    const float* Wq = (const float*)d_in[1];
    const float* Wk = (const float*)d_in[2];
    const float* Wv = (const float*)d_in[3];
    const float* Wo = (const float*)d_in[4];
    const float* bo = (const float*)d_in[5];
    const float* W1 = (const float*)d_in[6];
    const float* b1 = (const float*)d_in[7];
    const float* W2 = (const float*)d_in[8];
    const float* b2 = (const float*)d_in[9];
    const float* g1  = (const float*)d_in[10];
    const float* be1 = (const float*)d_in[11];
    const float* g2  = (const float*)d_in[12];
    const float* be2 = (const float*)d_in[13];
    float* out = (float*)d_out;

    __half *h, *qkv, *at, *ff, *wqkv, *wo, *w1, *w2;
    cudaGetSymbolAddress((void**)&h, g_h);
    cudaGetSymbolAddress((void**)&qkv, g_qkv);
    cudaGetSymbolAddress((void**)&at, g_at);
    cudaGetSymbolAddress((void**)&ff, g_ff);
    cudaGetSymbolAddress((void**)&wqkv, g_wqkv);
    cudaGetSymbolAddress((void**)&wo, g_wo);
    cudaGetSymbolAddress((void**)&w1, g_w1);
    cudaGetSymbolAddress((void**)&w2, g_w2);

    auto k_qkv = mma_gemm<false,false,false,false,true>;
    auto k_wo  = mma_gemm<true,false,true,true,false>;
    auto k_ff1 = mma_gemm<true,true,false,false,true>;
    cudaFuncSetAttribute(k_qkv, cudaFuncAttributeMaxDynamicSharedMemorySize, SMEMB);
    cudaFuncSetAttribute(k_wo,  cudaFuncAttributeMaxDynamicSharedMemorySize, SMEMB);
    cudaFuncSetAttribute(k_ff1, cudaFuncAttributeMaxDynamicSharedMemorySize, SMEMB);
    cudaFuncSetAttribute(attn_mma_kernel, cudaFuncAttributeMaxDynamicSharedMemorySize, ASMEM);

    int nsm = 148, occ = 2;
    cudaDeviceGetAttribute(&nsm, cudaDevAttrMultiProcessorCount, 0);
    cudaOccupancyMaxActiveBlocksPerMultiprocessor(&occ, k_qkv, 256, SMEMB);
    if (occ < 1) occ = 1;
    const int pgrid = nsm * occ;
    auto pg = [&](int ntiles) { return ntiles < pgrid ? ntiles : pgrid; };

    const int t4_ne = NE * NE / 4;      // 262144 -> 1024 blocks
    const int t4_ff = NE * FF / 4;      // 1048576 -> 4096 blocks

    wconv_qkv_kernel<<<dim3(t4_ne/256, 3), 256>>>(Wq, Wk, Wv, wqkv);       // 0
    wconv_kernel<<<t4_ne/256, 256>>>(Wo, wo, NE, t4_ne);                   // 1
    ln_kernel<<<BT/8, 256>>>(x, g1, be1, h);                               // 2
    mma_gemm<false,false,false,false,true><<<pg(768), 256, SMEMB>>>(
        h, wqkv, nullptr, nullptr, nullptr, qkv, BT, SQ3, NE, SQ3/128);    // 3
    dim3 gAtt(TT/128, BB*NH);
    attn_mma_kernel<<<gAtt, 256, ASMEM>>>(qkv, at);                        // 4
    mma_gemm<true,false,true,true,false><<<pg(256), 256, SMEMB>>>(
        at, wo, bo, x, out, nullptr, BT, NE, NE, NE/128);                  // 5
    ln_kernel<<<BT/8, 256>>>(out, g2, be2, h);                             // 6
    wconv_kernel<<<t4_ff/256, 256>>>(W1, w1, FF, t4_ff);                   // 7
    mma_gemm<true,true,false,false,true><<<pg(1024), 256, SMEMB>>>(
        h, w1, b1, nullptr, nullptr, ff, BT, FF, NE, FF/128);              // 8
    wconv_kernel<<<t4_ff/256, 256>>>(W2, w2, NE, t4_ff);                   // 9
    mma_gemm<true,false,true,true,false><<<pg(1024), 256, SMEMB>>>(
        ff, w2, b2, out, out, nullptr, BT, NE, FF, NE/128);                // 10
}

// round 13
// speedup vs baseline: 1.2283x; 1.0633x over previous
#include <cuda_runtime.h>
#include <cuda_fp16.h>
#include <cstdint>
#include <math.h>

// Problem constants
#define NE    1024
#define NH    16
#define HS    64
#define TT    2048
#define BB    2
#define BT    (BB*TT)   // 4096
#define FF    4096
#define LN_EPS 1e-5f
#define SQ3   (3*NE)    // fused qkv row stride

// ---------------- scratch (device globals) ----------------
__device__ __half g_h[(size_t)BT*NE];
__device__ __half g_qkv[(size_t)BT*SQ3];
__device__ __half g_at[(size_t)BT*NE];
__device__ __half g_ff[(size_t)BT*FF];
// fp16 weights, SAME [K,N] layout as source (no transpose)
__device__ __half g_wqkv[(size_t)NE*SQ3];   // [1024][3072] = Wq|Wk|Wv
__device__ __half g_wo[(size_t)NE*NE];
__device__ __half g_w1[(size_t)NE*FF];
__device__ __half g_w2[(size_t)FF*NE];

// ---------------- PTX helpers ----------------
__device__ __forceinline__ uint32_t smem_u32(const void* p) {
    uint32_t a;
    asm("{ .reg .u64 t; cvta.to.shared.u64 t, %1; cvt.u32.u64 %0, t; }" : "=r"(a) : "l"(p));
    return a;
}

__device__ __forceinline__ void ldsm4(uint32_t* r, uint32_t addr) {
    asm volatile("ldmatrix.sync.aligned.m8n8.x4.shared.b16 {%0,%1,%2,%3}, [%4];"
        : "=r"(r[0]), "=r"(r[1]), "=r"(r[2]), "=r"(r[3]) : "r"(addr));
}

__device__ __forceinline__ void ldsm4t(uint32_t* r, uint32_t addr) {
    asm volatile("ldmatrix.sync.aligned.m8n8.x4.trans.shared.b16 {%0,%1,%2,%3}, [%4];"
        : "=r"(r[0]), "=r"(r[1]), "=r"(r[2]), "=r"(r[3]) : "r"(addr));
}

__device__ __forceinline__ void mma16816(float* c, const uint32_t* a, const uint32_t* b) {
    asm volatile("mma.sync.aligned.m16n8k16.row.col.f32.f16.f16.f32 "
        "{%0,%1,%2,%3}, {%4,%5,%6,%7}, {%8,%9}, {%0,%1,%2,%3};"
        : "+f"(c[0]), "+f"(c[1]), "+f"(c[2]), "+f"(c[3])
        : "r"(a[0]), "r"(a[1]), "r"(a[2]), "r"(a[3]), "r"(b[0]), "r"(b[1]));
}

__device__ __forceinline__ uint32_t packh(float a, float b) {
    __half2 t = __floats2half2_rn(a, b);
    return *(uint32_t*)&t;
}

// ---------------- weight fp32 -> fp16 streaming casts ----------------
__global__ __launch_bounds__(256) void wconv_qkv_kernel(
    const float* __restrict__ Wq, const float* __restrict__ Wk,
    const float* __restrict__ Wv, __half* __restrict__ T)
{
    const float* W = (blockIdx.y == 0) ? Wq : (blockIdx.y == 1) ? Wk : Wv;
    const int colOff = blockIdx.y * NE;
    const int idx = blockIdx.x * 256 + threadIdx.x;     // NE*NE/4 chunks
    const int e = idx * 4;
    const int k = e >> 10, n = e & 1023;
    const float4 v = *(const float4*)(W + (size_t)k * NE + n);
    __half* o = T + (size_t)k * SQ3 + colOff + n;
    *(__half2*)o       = __floats2half2_rn(v.x, v.y);
    *(__half2*)(o + 2) = __floats2half2_rn(v.z, v.w);
}

__global__ __launch_bounds__(256) void wconv_kernel(
    const float* __restrict__ W, __half* __restrict__ T,
    int N, int total4)
{
    const int idx = blockIdx.x * 256 + threadIdx.x;
    if (idx >= total4) return;
    const int e = idx * 4;
    const int k = e / N, n = e - k * N;
    const float4 v = *(const float4*)(W + (size_t)k * N + n);
    __half* o = T + (size_t)k * N + n;
    *(__half2*)o       = __floats2half2_rn(v.x, v.y);
    *(__half2*)(o + 2) = __floats2half2_rn(v.z, v.w);
}

// ---------------- LayerNorm -> fp16, warp-per-row ----------------
__global__ __launch_bounds__(256) void ln_kernel(
    const float* __restrict__ X, const float* __restrict__ G,
    const float* __restrict__ Be, __half* __restrict__ Y)
{
    const int warp = threadIdx.x >> 5, lane = threadIdx.x & 31;
    const int row = blockIdx.x * 8 + warp;
    const float4* xr = (const float4*)(X + (size_t)row * NE);

    float4 xv[8];
    float s = 0.f, ss = 0.f;
    #pragma unroll
    for (int i = 0; i < 8; i++) {
        xv[i] = xr[i * 32 + lane];
        s  += xv[i].x + xv[i].y + xv[i].z + xv[i].w;
        ss += xv[i].x*xv[i].x + xv[i].y*xv[i].y + xv[i].z*xv[i].z + xv[i].w*xv[i].w;
    }
    #pragma unroll
    for (int o = 16; o > 0; o >>= 1) {
        s  += __shfl_xor_sync(0xffffffffu, s, o);
        ss += __shfl_xor_sync(0xffffffffu, ss, o);
    }
    const float mu   = s * (1.0f / NE);
    const float var  = ss * (1.0f / NE) - mu * mu;
    const float rstd = rsqrtf(var + LN_EPS);

    __half2* yp = (__half2*)(Y + (size_t)row * NE);
    #pragma unroll
    for (int i = 0; i < 8; i++) {
        const float4 gv = ((const float4*)G)[i * 32 + lane];
        const float4 bv = ((const float4*)Be)[i * 32 + lane];
        const int e2 = (i * 32 + lane) * 2;
        yp[e2]     = __floats2half2_rn((xv[i].x - mu) * rstd * gv.x + bv.x,
                                       (xv[i].y - mu) * rstd * gv.y + bv.y);
        yp[e2 + 1] = __floats2half2_rn((xv[i].z - mu) * rstd * gv.z + bv.z,
                                       (xv[i].w - mu) * rstd * gv.w + bv.w);
    }
}

// ---------------- persistent mma.sync fp16 GEMM (fp32 accum), B natural [K,N] ----------------
// 5-stage cp.async pipeline, ONE __syncthreads per K-step.
#define BK 32
#define STAGES 5
#define PREF (STAGES-1)              // prefetch depth 4, wait_group 3
#define AROWBG 80
#define AMATBG (128*AROWBG)          // 10240
#define BROWBG 272                   // 128 fp16 = 256B data + 16B pad
#define BMATBG (32*BROWBG)           // 8704
#define STAGEB (AMATBG + BMATBG)     // 18944
#define SMEMB (STAGES*STAGEB)        // 94720

template<bool BIAS, bool RELU, bool RES, bool OUTF32, bool OUTH>
__global__ __launch_bounds__(256) void mma_gemm(
    const __half* __restrict__ A, const __half* __restrict__ B,
    const float* __restrict__ bias, const float* __restrict__ res,
    float* __restrict__ Cf, __half* __restrict__ Ch,
    int M, int N, int K, int ntn)
{
    extern __shared__ char smem[];
    const uint32_t sb = smem_u32(smem);
    const int tid = threadIdx.x;
    const int warp = tid >> 5, lane = tid & 31;
    const int Ku4 = K >> 3, Nu4 = N >> 3;
    const int nch = K / BK;
    const int ntiles = (M >> 7) * ntn;

    const int wm = (warp >> 2) * 64;
    const int wn = (warp & 3) * 32;
    const int amat = lane >> 3;
    const int arr  = ((amat & 1) << 3) + (lane & 7);
    const int brow  = ((amat & 1) << 3) + (lane & 7);
    const int bhsel = lane >> 4;
    const int qrow = lane >> 2, qcol = (lane & 3) * 2;

    for (int tile = blockIdx.x; tile < ntiles; tile += gridDim.x) {
        const int m0 = (tile / ntn) << 7;
        const int n0 = (tile - (tile / ntn) * ntn) << 7;

        auto issue = [&](int kc, int s) {
            if (kc < nch) {
                const uint32_t stage = sb + (uint32_t)s * STAGEB;
                #pragma unroll
                for (int q = 0; q < 4; q++) {
                    const int idx = q * 256 + tid;
                    if (idx < 512) {            // A: 128 rows x 4 chunks
                        const int row = idx >> 2, u = idx & 3;
                        const uint4* g = (const uint4*)A + (size_t)(m0 + row) * Ku4 + kc * 4 + u;
                        const uint32_t sa = stage + row * AROWBG + u * 16;
                        asm volatile("cp.async.cg.shared.global [%0], [%1], 16;"
                                     :: "r"(sa), "l"(g));
                    } else {                    // B: 32 k-rows x 16 chunks
                        const int wi = idx - 512;
                        const int row = wi >> 4, u = wi & 15;
                        const uint4* g = (const uint4*)B + (size_t)(kc * 32 + row) * Nu4 + (n0 >> 3) + u;
                        const uint32_t sa = stage + AMATBG + row * BROWBG + u * 16;
                        asm volatile("cp.async.cg.shared.global [%0], [%1], 16;"
                                     :: "r"(sa), "l"(g));
                    }
                }
            }
            asm volatile("cp.async.commit_group;" ::: "memory");
        };

        float acc[4][4][4];
        #pragma unroll
        for (int i = 0; i < 4; i++)
            #pragma unroll
            for (int j = 0; j < 4; j++)
                #pragma unroll
                for (int r = 0; r < 4; r++) acc[i][j][r] = 0.f;

        #pragma unroll
        for (int p = 0; p < PREF; p++) issue(p, p);

        for (int kc = 0; kc < nch; kc++) {
            const int s = kc % STAGES;
            // 4 groups in flight (kc..kc+3); retire kc.
            asm volatile("cp.async.wait_group %0;" :: "n"(PREF - 1) : "memory");
            __syncthreads();   // all warps done reading stage (kc-1)%S -> safe to overwrite
            issue(kc + PREF, (kc + PREF) % STAGES);

            const uint32_t stage = sb + (uint32_t)s * STAGEB;
            const uint32_t aBase = stage;
            const uint32_t bBase = stage + AMATBG;

            // load ks=0 fragments
            uint32_t ah0[4][4], bh0[4][2], ah1[4][4], bh1[4][2];
            {
                const int au = (amat >> 1);
                #pragma unroll
                for (int i = 0; i < 4; i++)
                    ldsm4(ah0[i], aBase + (uint32_t)((wm + i * 16 + arr) * AROWBG + au * 16));
                #pragma unroll
                for (int jp = 0; jp < 2; jp++) {
                    uint32_t t[4];
                    ldsm4t(t, bBase + (uint32_t)((0 * 16 + brow) * BROWBG
                                                 + (wn + jp * 16) * 2 + bhsel * 16));
                    bh0[jp*2][0] = t[0]; bh0[jp*2][1] = t[1];
                    bh0[jp*2+1][0] = t[2]; bh0[jp*2+1][1] = t[3];
                }
            }
            // load ks=1 fragments (overlaps ks=0 MMAs below)
            {
                const int au = 2 + (amat >> 1);
                #pragma unroll
                for (int i = 0; i < 4; i++)
                    ldsm4(ah1[i], aBase + (uint32_t)((wm + i * 16 + arr) * AROWBG + au * 16));
                #pragma unroll
                for (int jp = 0; jp < 2; jp++) {
                    uint32_t t[4];
                    ldsm4t(t, bBase + (uint32_t)((1 * 16 + brow) * BROWBG
                                                 + (wn + jp * 16) * 2 + bhsel * 16));
                    bh1[jp*2][0] = t[0]; bh1[jp*2][1] = t[1];
                    bh1[jp*2+1][0] = t[2]; bh1[jp*2+1][1] = t[3];
                }
            }
            #pragma unroll
            for (int i = 0; i < 4; i++)
                #pragma unroll
                for (int j = 0; j < 4; j++) mma16816(acc[i][j], ah0[i], bh0[j]);
            #pragma unroll
            for (int i = 0; i < 4; i++)
                #pragma unroll
                for (int j = 0; j < 4; j++) mma16816(acc[i][j], ah1[i], bh1[j]);
        }
        asm volatile("cp.async.wait_group 0;" ::: "memory");

        #pragma unroll
        for (int i = 0; i < 4; i++) {
            #pragma unroll
            for (int j = 0; j < 4; j++) {
                const int col = n0 + wn + j * 8 + qcol;
                float2 bv = make_float2(0.f, 0.f);
                if (BIAS) bv = *(const float2*)(bias + col);
                #pragma unroll
                for (int half_ = 0; half_ < 2; half_++) {
                    const int row = m0 + wm + i * 16 + qrow + half_ * 8;
                    float v0 = acc[i][j][half_ * 2 + 0];
                    float v1 = acc[i][j][half_ * 2 + 1];
                    if (BIAS) { v0 += bv.x; v1 += bv.y; }
                    if (RELU) { v0 = fmaxf(v0, 0.f); v1 = fmaxf(v1, 0.f); }
                    if (RES) {
                        float2 r = *(const float2*)(res + (size_t)row * N + col);
                        v0 += r.x; v1 += r.y;
                    }
                    if (OUTF32)
                        *(float2*)(Cf + (size_t)row * N + col) = make_float2(v0, v1);
                    if (OUTH)
                        *(__half2*)(Ch + (size_t)row * N + col) = __floats2half2_rn(v0, v1);
                }
            }
        }
        __syncthreads();   // guard smem reuse across tiles
    }
}

// ---------------- tensor-core causal flash attention (fp16, fused-qkv input) ----------------
#define AROWB 144
#define AQMAT (128*AROWB)               // 18432
#define AKMAT (64*AROWB)                // 9216
#define ASTAGE (2*AKMAT)                // K, V
#define ASMEM (AQMAT + 2*ASTAGE)        // 55296

__global__ __launch_bounds__(256) void attn_mma_kernel(
    const __half* __restrict__ QKV, __half* __restrict__ O)
{
    extern __shared__ char smem[];
    const uint32_t sb = smem_u32(smem);
    const int tid = threadIdx.x, warp = tid >> 5, lane = tid & 31;
    const int bh = blockIdx.y, b = bh >> 4, h = bh & 15;
    const int qt = gridDim.x - 1 - blockIdx.x;     // heavy tiles first
    const int q0 = qt * 128;
    const size_t qbase = (size_t)b * TT * SQ3 + h * HS;
    const size_t obase = (size_t)b * TT * NE + h * HS;

    {
        #pragma unroll
        for (int c = 0; c < 4; c++) {
            const int idx = c * 256 + tid;
            const int row = idx >> 3, u = idx & 7;
            const uint4* g = (const uint4*)(QKV + qbase + (size_t)(q0 + row) * SQ3) + u;
            const uint32_t sa = sb + row * AROWB + u * 16;
            asm volatile("cp.async.cg.shared.global [%0], [%1], 16;" :: "r"(sa), "l"(g));
        }
        asm volatile("cp.async.commit_group;" ::: "memory");
    }

    auto issue_kv = [&](int t, int s) {
        if (t >= 0) {
            const int k0 = t * 64;
            const uint32_t stage = sb + AQMAT + (uint32_t)s * ASTAGE;
            #pragma unroll
            for (int c = 0; c < 4; c++) {
                const int idx = c * 256 + tid;
                const int mat = idx >> 9, wi = idx & 511;
                const int row = wi >> 3, u = wi & 7;
                const uint4* g = (const uint4*)(QKV + qbase + (mat + 1) * NE
                                                + (size_t)(k0 + row) * SQ3) + u;
                const uint32_t sa = stage + mat * AKMAT + row * AROWB + u * 16;
                asm volatile("cp.async.cg.shared.global [%0], [%1], 16;" :: "r"(sa), "l"(g));
            }
        }
        asm volatile("cp.async.commit_group;" ::: "memory");
    };

    const int ntiles = 2 * (qt + 1);
    issue_kv(0, 0);

    float m[2] = { -1e30f, -1e30f }, l[2] = { 0.f, 0.f };
    float o[8][4];
    #pragma unroll
    for (int nt = 0; nt < 8; nt++)
        #pragma unroll
        for (int e = 0; e < 4; e++) o[nt][e] = 0.f;

    const float scale = 0.03125f;   // 1024^-0.5, faithful to source
    const int amat = lane >> 3;
    const int arr  = ((amat & 1) << 3) + (lane & 7);
    const int ahalf = amat >> 1;
    const int brr  = ((amat >> 1) << 3) + (lane & 7);
    const int bhalf = amat & 1;
    const int vrow  = ((amat & 1) << 3) + (lane & 7);
    const int vhalf = lane >> 4;

    for (int t = 0; t < ntiles; t++) {
        issue_kv((t + 1 < ntiles) ? t + 1 : -1, (t + 1) & 1);
        asm volatile("cp.async.wait_group 1;" ::: "memory");
        __syncthreads();

        const int k0 = t * 64;
        const uint32_t stage = sb + AQMAT + (uint32_t)(t & 1) * ASTAGE;
        const uint32_t kB = stage, vB = stage + AKMAT;

        float s[8][4];
        #pragma unroll
        for (int nt = 0; nt < 8; nt++)
            #pragma unroll
            for (int e = 0; e < 4; e++) s[nt][e] = 0.f;

        #pragma unroll
        for (int kc = 0; kc < 4; kc++) {
            uint32_t af[4];
            ldsm4(af, sb + (uint32_t)((warp * 16 + arr) * AROWB + kc * 32 + ahalf * 16));
            #pragma unroll
            for (int jp = 0; jp < 4; jp++) {
                uint32_t tt[4];
                ldsm4(tt, kB + (uint32_t)((jp * 16 + brr) * AROWB + kc * 32 + bhalf * 16));
                uint32_t b0[2] = { tt[0], tt[1] }, b1[2] = { tt[2], tt[3] };
                mma16816(s[jp * 2],     af, b0);
                mma16816(s[jp * 2 + 1], af, b1);
            }
        }

        const bool domask = (k0 + 63 > q0);
        float mnew[2] = { m[0], m[1] };
        #pragma unroll
        for (int nt = 0; nt < 8; nt++)
            #pragma unroll
            for (int e = 0; e < 4; e++) {
                float v = s[nt][e] * scale;
                if (domask) {
                    const int key = k0 + nt * 8 + (lane & 3) * 2 + (e & 1);
                    const int qq  = q0 + warp * 16 + (lane >> 2) + (e >> 1) * 8;
                    if (key > qq) v = -1e30f;
                }
                s[nt][e] = v;
                mnew[e >> 1] = fmaxf(mnew[e >> 1], v);
            }
        #pragma unroll
        for (int r = 0; r < 2; r++) {
            mnew[r] = fmaxf(mnew[r], __shfl_xor_sync(0xffffffffu, mnew[r], 1));
            mnew[r] = fmaxf(mnew[r], __shfl_xor_sync(0xffffffffu, mnew[r], 2));
        }
        float corr[2], psum[2] = { 0.f, 0.f };
        corr[0] = __expf(m[0] - mnew[0]);
        corr[1] = __expf(m[1] - mnew[1]);
        m[0] = mnew[0]; m[1] = mnew[1];
        #pragma unroll
        for (int nt = 0; nt < 8; nt++)
            #pragma unroll
            for (int e = 0; e < 4; e++) {
                const float p_ = __expf(s[nt][e] - mnew[e >> 1]);
                s[nt][e] = p_;
                psum[e >> 1] += p_;
            }
        #pragma unroll
        for (int r = 0; r < 2; r++) {
            psum[r] += __shfl_xor_sync(0xffffffffu, psum[r], 1);
            psum[r] += __shfl_xor_sync(0xffffffffu, psum[r], 2);
            l[r] = l[r] * corr[r] + psum[r];
        }
        #pragma unroll
        for (int nt = 0; nt < 8; nt++)
            #pragma unroll
            for (int e = 0; e < 4; e++) o[nt][e] *= corr[e >> 1];

        #pragma unroll
        for (int kk = 0; kk < 4; kk++) {
            uint32_t ph[4];
            ph[0] = packh(s[2*kk][0],   s[2*kk][1]);
            ph[1] = packh(s[2*kk][2],   s[2*kk][3]);
            ph[2] = packh(s[2*kk+1][0], s[2*kk+1][1]);
            ph[3] = packh(s[2*kk+1][2], s[2*kk+1][3]);
            #pragma unroll
            for (int jp = 0; jp < 4; jp++) {
                const uint32_t va =
                    (uint32_t)((kk * 16 + vrow) * AROWB + jp * 32 + vhalf * 16);
                uint32_t th[4];
                ldsm4t(th, vB + va);
                uint32_t bh0[2] = { th[0], th[1] }, bh1[2] = { th[2], th[3] };
                mma16816(o[jp*2],   ph, bh0);
                mma16816(o[jp*2+1], ph, bh1);
            }
        }
        __syncthreads();   // LOAD-BEARING here: next iter's issue overwrites this stage
    }

    const float inv0 = 1.0f / l[0], inv1 = 1.0f / l[1];
    const int r0 = q0 + warp * 16 + (lane >> 2);
    const int r1 = r0 + 8;
    #pragma unroll
    for (int nt = 0; nt < 8; nt++) {
        const int col = nt * 8 + (lane & 3) * 2;
        *(__half2*)(O + obase + (size_t)r0 * NE + col) =
            __floats2half2_rn(o[nt][0] * inv0, o[nt][1] * inv0);
        *(__half2*)(O + obase + (size_t)r1 * NE + col) =
            __floats2half2_rn(o[nt][2] * inv1, o[nt][3] * inv1);
    }
}

// ---------------- launch ----------------
extern "C" void kernel_launch(void* const* d_in, const int* in_sizes, int n_in,
                              void* d_out, int out_size)
{
    const float* x  = (const float*)d_in[0];
    const float* Wq = (const float*)d_in[1];
    const float* Wk = (const float*)d_in[2];
    const float* Wv = (const float*)d_in[3];
    const float* Wo = (const float*)d_in[4];
    const float* bo = (const float*)d_in[5];
    const float* W1 = (const float*)d_in[6];
    const float* b1 = (const float*)d_in[7];
    const float* W2 = (const float*)d_in[8];
    const float* b2 = (const float*)d_in[9];
    const float* g1  = (const float*)d_in[10];
    const float* be1 = (const float*)d_in[11];
    const float* g2  = (const float*)d_in[12];
    const float* be2 = (const float*)d_in[13];
    float* out = (float*)d_out;

    __half *h, *qkv, *at, *ff, *wqkv, *wo, *w1, *w2;
    cudaGetSymbolAddress((void**)&h, g_h);
    cudaGetSymbolAddress((void**)&qkv, g_qkv);
    cudaGetSymbolAddress((void**)&at, g_at);
    cudaGetSymbolAddress((void**)&ff, g_ff);
    cudaGetSymbolAddress((void**)&wqkv, g_wqkv);
    cudaGetSymbolAddress((void**)&wo, g_wo);
    cudaGetSymbolAddress((void**)&w1, g_w1);
    cudaGetSymbolAddress((void**)&w2, g_w2);

    auto k_qkv = mma_gemm<false,false,false,false,true>;
    auto k_wo  = mma_gemm<true,false,true,true,false>;
    auto k_ff1 = mma_gemm<true,true,false,false,true>;
    cudaFuncSetAttribute(k_qkv, cudaFuncAttributeMaxDynamicSharedMemorySize, SMEMB);
    cudaFuncSetAttribute(k_wo,  cudaFuncAttributeMaxDynamicSharedMemorySize, SMEMB);
    cudaFuncSetAttribute(k_ff1, cudaFuncAttributeMaxDynamicSharedMemorySize, SMEMB);
    cudaFuncSetAttribute(attn_mma_kernel, cudaFuncAttributeMaxDynamicSharedMemorySize, ASMEM);

    int nsm = 148, occ = 2;
    cudaDeviceGetAttribute(&nsm, cudaDevAttrMultiProcessorCount, 0);
    cudaOccupancyMaxActiveBlocksPerMultiprocessor(&occ, k_qkv, 256, SMEMB);
    if (occ < 1) occ = 1;
    const int pgrid = nsm * occ;
    auto pg = [&](int ntiles) { return ntiles < pgrid ? ntiles : pgrid; };

    const int t4_ne = NE * NE / 4;      // 262144 -> 1024 blocks
    const int t4_ff = NE * FF / 4;      // 1048576 -> 4096 blocks

    wconv_qkv_kernel<<<dim3(t4_ne/256, 3), 256>>>(Wq, Wk, Wv, wqkv);       // 0
    wconv_kernel<<<t4_ne/256, 256>>>(Wo, wo, NE, t4_ne);                   // 1
    ln_kernel<<<BT/8, 256>>>(x, g1, be1, h);                               // 2
    mma_gemm<false,false,false,false,true><<<pg(768), 256, SMEMB>>>(
        h, wqkv, nullptr, nullptr, nullptr, qkv, BT, SQ3, NE, SQ3/128);    // 3
    dim3 gAtt(TT/128, BB*NH);
    attn_mma_kernel<<<gAtt, 256, ASMEM>>>(qkv, at);                        // 4
    mma_gemm<true,false,true,true,false><<<pg(256), 256, SMEMB>>>(
        at, wo, bo, x, out, nullptr, BT, NE, NE, NE/128);                  // 5
    ln_kernel<<<BT/8, 256>>>(out, g2, be2, h);                             // 6
    wconv_kernel<<<t4_ff/256, 256>>>(W1, w1, FF, t4_ff);                   // 7
    mma_gemm<true,true,false,false,true><<<pg(1024), 256, SMEMB>>>(
        h, w1, b1, nullptr, nullptr, ff, BT, FF, NE, FF/128);              // 8
    wconv_kernel<<<t4_ff/256, 256>>>(W2, w2, NE, t4_ff);                   // 9
    mma_gemm<true,false,true,true,false><<<pg(1024), 256, SMEMB>>>(
        ff, w2, b2, out, out, nullptr, BT, NE, FF, NE/128);                // 10
}